// round 5
// baseline (speedup 1.0000x reference)
#include <cuda_runtime.h>
#include <cuda_bf16.h>

#define F_DIM 35
#define T_MAX 512
#define LOG2E 1.4426950408889634f
#define LN2   0.6931471805599453f
#define DRIFT 8
#define CDEAD (-(1 << 28))

__device__ float g_partials[1024];
__device__ int   g_count = 0;

__device__ __forceinline__ float ex2f(float x) {
    float r; asm("ex2.approx.ftz.f32 %0, %1;" : "=f"(r) : "f"(x)); return r;
}
__device__ __forceinline__ float lg2f(float x) {
    float r; asm("lg2.approx.ftz.f32 %0, %1;" : "=f"(r) : "f"(x)); return r;
}
__device__ __forceinline__ float pow2i(int e) {   // 2^e for e in [-127, 127]
    return __uint_as_float((unsigned)(127 + e) << 23);  // e == -127 -> +0
}

// 128 threads/CTA; thread k owns extended states 2k (blank) and 2k+1 (label k).
// Linear-domain recursion (lse == add, zero MUFU in the loop) with PER-THREAD
// power-of-2 reference exponents, re-smoothed every 8 frames by a
// prefix-max-with-drift scan so adjacent refs differ by at most DRIFT.
__global__ __launch_bounds__(128, 8) void sctc_fused_kernel(
    const float* __restrict__ logits,        // (B,T,F)
    const float* __restrict__ blank_logit,   // (1,)
    const int*   __restrict__ targets,       // (B,S,F)
    const int*   __restrict__ input_lengths, // (B,)
    const int*   __restrict__ target_lengths,// (B,)
    float* __restrict__ out,
    int B, int T, int S)
{
    __shared__ float P[3][T_MAX];   // linear softmax probs
    __shared__ float mail[2][4];    // warp-boundary alpha_odd, double-buffered
    __shared__ int   warpC[4];      // per-warp scan carry
    __shared__ int   mailR[4];      // warp-boundary refs
    __shared__ float AeF[128];
    __shared__ float AoF[128];
    __shared__ int   RF[128];

    const int bx   = blockIdx.x;
    const int b    = bx / F_DIM;
    const int f    = bx - b * F_DIM;
    const int tid  = threadIdx.x;
    const int lane = tid & 31;
    const int w    = tid >> 5;
    const int k    = tid;

    const float ub = blank_logit[0] * LOG2E;

    // ---- linear 3-class softmax for every frame of this (b,f) ----
    for (int t = tid; t < T; t += 128) {
        float u  = logits[(b * T + t) * F_DIM + f] * LOG2E;
        float m  = fmaxf(fabsf(u), ub);
        float s0 = ex2f(-u - m);
        float s1 = ex2f( u - m);
        float s2 = ex2f(ub - m);
        float iv = 1.0f / (s0 + s1 + s2);   // precise division (preamble only)
        P[0][t] = s0 * iv;
        P[1][t] = s1 * iv;
        P[2][t] = s2 * iv;
    }

    // ---- transition structure ----
    float skipf = 0.0f;
    const float* pl = &P[2][0];
    if (k < S) {
        int lab = targets[(b * S + k) * F_DIM + f];
        pl = &P[lab][0];
        if (k >= 1) skipf = (lab != targets[(b * S + k - 1) * F_DIM + f]) ? 1.0f : 0.0f;
    }
    const float* pb = &P[2][0];

    __syncthreads();

    // ---- init at t=0 ----
    float ae = 0.0f, ao = 0.0f;
    if (k == 0) { ae = pb[0]; ao = pl[0]; }
    int   R    = 0;       // true_alpha = stored * 2^R
    float scIn = 0.0f;    // scale applied to incoming neighbor value

    // ================= normalize macro (uniform control flow) =================
#define NORMALIZE()                                                            \
    {                                                                          \
        float mv = fmaxf(ae, ao);                                              \
        int C = (mv > 0.0f)                                                    \
              ? (R + (int)((__float_as_uint(mv) >> 23) & 255u) - 127)          \
              : CDEAD;                                                         \
        _Pragma("unroll")                                                      \
        for (int o = 1; o < 32; o <<= 1) {                                     \
            int cu = __shfl_up_sync(0xffffffffu, C, o);                        \
            if (lane >= o) C = max(C, cu - DRIFT * o);                         \
        }                                                                      \
        if (lane == 31) warpC[w] = C;                                          \
        __syncthreads();                                                       \
        _Pragma("unroll")                                                      \
        for (int j = 0; j < 3; ++j)                                            \
            if (j < w) C = max(C, warpC[j] - DRIFT * (k - (32 * j + 31)));     \
        int Rn = C;                                                            \
        if (lane == 31) mailR[w] = Rn;                                         \
        __syncthreads();                                                       \
        int Rp = __shfl_up_sync(0xffffffffu, Rn, 1);                           \
        if (lane == 0) Rp = (w == 0) ? (Rn - 200) : mailR[w - 1];              \
        int d = Rp - Rn;                     /* <= DRIFT by construction */    \
        scIn = (d < -127) ? 0.0f : pow2i(d);                                   \
        int sh  = R - Rn;                                                      \
        int s1c = max(-127, min(127, sh));                                     \
        int s2c = max(-127, min(127, sh - s1c));                               \
        float fs = pow2i(s1c), fs2 = pow2i(s2c);                               \
        ae = (ae * fs) * fs2;                                                  \
        ao = (ao * fs) * fs2;                                                  \
        R  = Rn;                                                               \
    }
    // =========================================================================

    NORMALIZE();
    if (lane == 31) mail[0][w] = ao;
    __syncthreads();

    const int Tin = input_lengths[b];

    for (int t = 1; t < Tin; ++t) {
        float ao_prev = __shfl_up_sync(0xffffffffu, ao, 1);
        if (lane == 0) ao_prev = (w == 0) ? 0.0f : mail[(t - 1) & 1][w - 1];
        float t1 = ao_prev * scIn;           // neighbor rebased to our frame

        float pbt = pb[t];
        float plt = pl[t];
        float ae_new = (ae + t1) * pbt;
        float ao_new = __fmaf_rn(skipf, t1, ao + ae) * plt;
        ae = ae_new;
        ao = ao_new;

        if ((t & 7) == 0) NORMALIZE();

        if (lane == 31) mail[t & 1][w] = ao;
        __syncthreads();
    }

    // ---- spill final (value, ref) pairs; thread 0 finalizes ----
    AeF[tid] = ae;
    AoF[tid] = ao;
    RF[tid]  = R;
    __syncthreads();

    bool isLast = false;
    if (tid == 0) {
        int   Lt = target_lengths[b];
        float v1 = AeF[Lt];     int r1 = RF[Lt];       // alpha[2L]
        float v2 = AoF[Lt - 1]; int r2 = RF[Lt - 1];   // alpha[2L-1]
        int   Rm = max(r1, r2);
        int   d1 = r1 - Rm, d2 = r2 - Rm;
        float w1 = (d1 < -127) ? 0.0f : pow2i(d1);
        float w2 = (d2 < -127) ? 0.0f : pow2i(d2);
        float v  = v1 * w1 + v2 * w2;
        float ll2  = lg2f(v) + (float)Rm;    // lg2f(0) = -inf -> loss = +inf
        float loss = -ll2 * LN2;
        if (!(loss <= 0.5e30f)) loss = 0.0f; // zero_infinity (also catches nan/inf)
        g_partials[bx] = loss / (float)Lt;
        __threadfence();
        int old = atomicAdd(&g_count, 1);
        isLast = (old == (int)gridDim.x - 1);
    }
    if (tid < 32) {
        int last = __shfl_sync(0xffffffffu, isLast ? 1 : 0, 0);
        if (last) {
            int   n  = gridDim.x;
            float sv = 0.0f;
            for (int j = tid; j < n; j += 32) sv += g_partials[j];
            #pragma unroll
            for (int o = 16; o; o >>= 1) sv += __shfl_down_sync(0xffffffffu, sv, o);
            if (tid == 0) {
                out[0] = sv / (float)n;
                g_count = 0;               // reset for next graph replay
            }
        }
    }
}

extern "C" void kernel_launch(void* const* d_in, const int* in_sizes, int n_in,
                              void* d_out, int out_size)
{
    const float* logits  = (const float*)d_in[0];
    const float* blankl  = (const float*)d_in[1];
    const int*   targets = (const int*)d_in[2];
    const int*   in_len  = (const int*)d_in[3];
    const int*   tg_len  = (const int*)d_in[4];

    const int B = in_sizes[3];
    const int T = in_sizes[0] / (B * F_DIM);
    const int S = in_sizes[2] / (B * F_DIM);
    const int nblk = B * F_DIM;

    sctc_fused_kernel<<<nblk, 128>>>(logits, blankl, targets, in_len, tg_len,
                                     (float*)d_out, B, T, S);
}

// round 6
// speedup vs baseline: 1.9103x; 1.9103x over previous
#include <cuda_runtime.h>
#include <cuda_bf16.h>

#define F_DIM   35
#define T_PAD   512
#define LOG2E   1.4426950408889634f
#define LN2     0.6931471805599453f
#define CDEAD   (-(1 << 28))
#define DRIFT_T 48

__device__ float g_partials[1024];
__device__ int   g_count = 0;

__device__ __forceinline__ float ex2f(float x) {
    float r; asm("ex2.approx.ftz.f32 %0, %1;" : "=f"(r) : "f"(x)); return r;
}
__device__ __forceinline__ float lg2f(float x) {
    float r; asm("lg2.approx.ftz.f32 %0, %1;" : "=f"(r) : "f"(x)); return r;
}
__device__ __forceinline__ float pow2i(int e) {   // 2^e, e in [-127,128]
    return __uint_as_float((unsigned)(127 + e) << 23);
}

// One WARP per (b,f) task; thread owns 4 contiguous state-pairs (8 states).
// Linear-domain CTC recursion: zero MUFU, zero __syncthreads in the loop;
// per-thread power-of-2 refs re-smoothed by an in-warp prefix scan every 8
// frames. The only cross-thread op per frame is one shfl_up.
__global__ __launch_bounds__(128, 1) void sctc_warp_kernel(
    const float* __restrict__ logits,        // (B,T,F)
    const float* __restrict__ blank_logit,   // (1,)
    const int*   __restrict__ targets,       // (B,S,F)
    const int*   __restrict__ input_lengths, // (B,)
    const int*   __restrict__ target_lengths,// (B,)
    float* __restrict__ out,
    int B, int T, int S, int nTasks)
{
    __shared__ float P[4][3][T_PAD];   // per-warp linear softmax probs
    __shared__ float AeF[4][128];      // final even alphas (per warp)
    __shared__ float AoF[4][128];      // final odd alphas
    __shared__ int   RF[4][32];        // final per-thread refs

    const int tid  = threadIdx.x;
    const int lane = tid & 31;
    const int w    = tid >> 5;
    int  task = blockIdx.x * 4 + w;
    bool live = (task < nTasks);
    if (!live) task = 0;
    const int b = task / F_DIM;
    const int f = task - b * F_DIM;

    const float ub = blank_logit[0] * LOG2E;
    float (*Pw)[T_PAD] = P[w];

    // ---- linear 3-class softmax for every frame of this (b,f) ----
    for (int t = lane; t < T; t += 32) {
        float u  = logits[(b * T + t) * F_DIM + f] * LOG2E;
        float m  = fmaxf(fabsf(u), ub);
        float s0 = ex2f(-u - m);
        float s1 = ex2f( u - m);
        float s2 = ex2f(ub - m);
        float iv = 1.0f / (s0 + s1 + s2);
        Pw[0][t] = s0 * iv;
        Pw[1][t] = s1 * iv;
        Pw[2][t] = s2 * iv;
    }

    // ---- per-pair transition structure (4 pairs per thread) ----
    const int p0 = lane * 4;
    bool  labB[4], vA[4];
    float skA[4];
    {
        const int base = b * S * F_DIM + f;
        int prev = (p0 >= 1 && p0 - 1 < S) ? targets[base + (p0 - 1) * F_DIM] : -1;
        #pragma unroll
        for (int i = 0; i < 4; ++i) {
            int p = p0 + i;
            if (p < S) {
                int l  = targets[base + p * F_DIM];
                labB[i] = (l != 0);
                vA[i]   = true;
                skA[i]  = (p >= 1 && l != prev) ? 1.0f : 0.0f;
                prev = l;
            } else {
                labB[i] = false; vA[i] = false; skA[i] = 0.0f; prev = -1;
            }
        }
    }
    __syncwarp();

    // ---- init at t=0 ----
    float ae[4] = {0.f, 0.f, 0.f, 0.f};
    float ao[4] = {0.f, 0.f, 0.f, 0.f};
    if (lane == 0) {
        ae[0] = Pw[2][0];
        ao[0] = labB[0] ? Pw[1][0] : Pw[0][0];
    }
    int   R    = 0;      // true_alpha = stored * 2^R
    float scIn = 0.0f;   // rebase factor for incoming left-neighbor value

#define NORM()                                                                  \
    {                                                                           \
        float mv = fmaxf(fmaxf(fmaxf(ae[0], ao[0]), fmaxf(ae[1], ao[1])),       \
                         fmaxf(fmaxf(ae[2], ao[2]), fmaxf(ae[3], ao[3])));      \
        int C = (mv > 0.0f)                                                     \
              ? (R + (int)((__float_as_uint(mv) >> 23) & 255u) - 127)           \
              : CDEAD;                                                          \
        _Pragma("unroll")                                                       \
        for (int o = 1; o < 32; o <<= 1) {                                      \
            int cu = __shfl_up_sync(0xffffffffu, C, o);                         \
            if (lane >= o) C = max(C, cu - DRIFT_T * o);                        \
        }                                                                       \
        int Rn = C;                                                             \
        int Rp = __shfl_up_sync(0xffffffffu, Rn, 1);                            \
        if (lane == 0) Rp = Rn - 200;                                           \
        int d = Rp - Rn;                          /* <= DRIFT_T by scan */      \
        scIn = (d < -127) ? 0.0f : pow2i(min(d, 127));                          \
        int sh = R - Rn;                                                        \
        int sa = max(-127, min(127, sh));                                       \
        int sb = max(-127, min(127, sh - sa));                                  \
        float fa = pow2i(sa), fb = pow2i(sb);                                   \
        _Pragma("unroll")                                                       \
        for (int i = 0; i < 4; ++i) { ae[i] = (ae[i]*fa)*fb; ao[i] = (ao[i]*fa)*fb; } \
        R = Rn;                                                                 \
    }

#define STEP(tt)                                                                \
    {                                                                           \
        float aoIn = __shfl_up_sync(0xffffffffu, ao[3], 1);                     \
        if (lane == 0) aoIn = 0.0f;                                             \
        float t1 = aoIn * scIn;                                                 \
        float pb = Pw[2][tt];                                                   \
        float q0 = Pw[0][tt];                                                   \
        float q1 = Pw[1][tt];                                                   \
        float pl0 = vA[0] ? (labB[0] ? q1 : q0) : 0.0f;                         \
        float pl1 = vA[1] ? (labB[1] ? q1 : q0) : 0.0f;                         \
        float pl2 = vA[2] ? (labB[2] ? q1 : q0) : 0.0f;                         \
        float pl3 = vA[3] ? (labB[3] ? q1 : q0) : 0.0f;                         \
        float nae0 = (ae[0] + t1)    * pb;                                      \
        float nao0 = __fmaf_rn(skA[0], t1,    ao[0] + ae[0]) * pl0;             \
        float nae1 = (ae[1] + ao[0]) * pb;                                      \
        float nao1 = __fmaf_rn(skA[1], ao[0], ao[1] + ae[1]) * pl1;             \
        float nae2 = (ae[2] + ao[1]) * pb;                                      \
        float nao2 = __fmaf_rn(skA[2], ao[1], ao[2] + ae[2]) * pl2;             \
        float nae3 = (ae[3] + ao[2]) * pb;                                      \
        float nao3 = __fmaf_rn(skA[3], ao[2], ao[3] + ae[3]) * pl3;             \
        ae[0] = nae0; ae[1] = nae1; ae[2] = nae2; ae[3] = nae3;                 \
        ao[0] = nao0; ao[1] = nao1; ao[2] = nao2; ao[3] = nao3;                 \
    }

    NORM();   // establishes scIn for the first window

    const int Tin = input_lengths[b];
    int t = 1;
    while (t + 8 <= Tin) {
        #pragma unroll
        for (int j = 0; j < 8; ++j) STEP(t + j);
        t += 8;
        NORM();
    }
    for (; t < Tin; ++t) STEP(t);

    // ---- spill final (value, ref); lane 0 finalizes this task ----
    #pragma unroll
    for (int i = 0; i < 4; ++i) { AeF[w][p0 + i] = ae[i]; AoF[w][p0 + i] = ao[i]; }
    RF[w][lane] = R;
    __syncwarp();

    if (lane == 0 && live) {
        int   Lt = target_lengths[b];
        float v1 = AeF[w][Lt];     int r1 = RF[w][Lt >> 2];        // alpha[2L]
        float v2 = AoF[w][Lt - 1]; int r2 = RF[w][(Lt - 1) >> 2];  // alpha[2L-1]
        int   Rm = max(r1, r2);
        float w1 = (r1 - Rm < -127) ? 0.0f : pow2i(r1 - Rm);
        float w2 = (r2 - Rm < -127) ? 0.0f : pow2i(r2 - Rm);
        float v  = v1 * w1 + v2 * w2;
        float ll2  = lg2f(v) + (float)Rm;     // lg2f(0) = -inf -> +inf loss
        float loss = -ll2 * LN2;
        if (!(loss <= 0.5e30f)) loss = 0.0f;  // zero_infinity (also nan/inf)
        g_partials[task] = loss / (float)Lt;
    }
    __syncthreads();

    // ---- fused deterministic reduction (last CTA) ----
    bool isLast = false;
    if (tid == 0) {
        __threadfence();
        int old = atomicAdd(&g_count, 1);
        isLast = (old == (int)gridDim.x - 1);
    }
    if (tid < 32) {
        int last = __shfl_sync(0xffffffffu, isLast ? 1 : 0, 0);
        if (last) {
            float sv = 0.0f;
            for (int j = lane; j < nTasks; j += 32) sv += g_partials[j];
            #pragma unroll
            for (int o = 16; o; o >>= 1) sv += __shfl_down_sync(0xffffffffu, sv, o);
            if (lane == 0) {
                out[0] = sv / (float)nTasks;
                g_count = 0;               // reset for next graph replay
            }
        }
    }
#undef STEP
#undef NORM
}

extern "C" void kernel_launch(void* const* d_in, const int* in_sizes, int n_in,
                              void* d_out, int out_size)
{
    const float* logits  = (const float*)d_in[0];
    const float* blankl  = (const float*)d_in[1];
    const int*   targets = (const int*)d_in[2];
    const int*   in_len  = (const int*)d_in[3];
    const int*   tg_len  = (const int*)d_in[4];

    const int B = in_sizes[3];
    const int T = in_sizes[0] / (B * F_DIM);
    const int S = in_sizes[2] / (B * F_DIM);
    const int nTasks = B * F_DIM;
    const int nblk   = (nTasks + 3) / 4;

    sctc_warp_kernel<<<nblk, 128>>>(logits, blankl, targets, in_len, tg_len,
                                    (float*)d_out, B, T, S, nTasks);
}

// round 7
// speedup vs baseline: 1.9570x; 1.0244x over previous
#include <cuda_runtime.h>
#include <cuda_bf16.h>

#define F_DIM   35
#define T_PAD   512
#define LOG2E   1.4426950408889634f
#define LN2     0.6931471805599453f
#define CDEAD   (-(1 << 28))
#define DRIFT_T 48

__device__ float g_partials[1024];
__device__ int   g_count = 0;

__device__ __forceinline__ float ex2f(float x) {
    float r; asm("ex2.approx.ftz.f32 %0, %1;" : "=f"(r) : "f"(x)); return r;
}
__device__ __forceinline__ float lg2f(float x) {
    float r; asm("lg2.approx.ftz.f32 %0, %1;" : "=f"(r) : "f"(x)); return r;
}
__device__ __forceinline__ float pow2i(int e) {   // 2^e, e in [-127,128]
    return __uint_as_float((unsigned)(127 + e) << 23);
}

// One WARP per (b,f) task; thread owns 4 contiguous state-pairs (8 states).
// Linear-domain CTC: zero MUFU / zero barriers in the loop. This revision:
//  - probs packed float4 -> one LDS.128 per step (hoistable in the unroll)
//  - shfl software-pipelined: pair 3 computed first, its shfl issued early,
//    result consumed only next step (26-cyc latency fully hidden)
//  - no validity masking (out-of-range states decay harmlessly, never read)
__global__ __launch_bounds__(128, 1) void sctc_warp_kernel(
    const float* __restrict__ logits,        // (B,T,F)
    const float* __restrict__ blank_logit,   // (1,)
    const int*   __restrict__ targets,       // (B,S,F)
    const int*   __restrict__ input_lengths, // (B,)
    const int*   __restrict__ target_lengths,// (B,)
    float* __restrict__ out,
    int B, int T, int S, int nTasks)
{
    __shared__ float4 P4[4][T_PAD];    // per-warp {q0, q1, pb, pad}
    __shared__ float  AeF[4][128];
    __shared__ float  AoF[4][128];
    __shared__ int    RF[4][32];

    const int tid  = threadIdx.x;
    const int lane = tid & 31;
    const int w    = tid >> 5;
    int  task = blockIdx.x * 4 + w;
    bool live = (task < nTasks);
    if (!live) task = 0;
    const int b = task / F_DIM;
    const int f = task - b * F_DIM;

    const float ub = blank_logit[0] * LOG2E;
    float4* Pw = P4[w];

    // ---- linear 3-class softmax, packed ----
    for (int t = lane; t < T; t += 32) {
        float u  = logits[(b * T + t) * F_DIM + f] * LOG2E;
        float m  = fmaxf(fabsf(u), ub);
        float s0 = ex2f(-u - m);
        float s1 = ex2f( u - m);
        float s2 = ex2f(ub - m);
        float iv = 1.0f / (s0 + s1 + s2);
        Pw[t] = make_float4(s0 * iv, s1 * iv, s2 * iv, 0.0f);
    }

    // ---- per-pair structure (no validity mask needed) ----
    const int p0 = lane * 4;
    bool  labB[4];
    float skA[4];
    {
        const int base = b * S * F_DIM + f;
        int prev = (p0 >= 1 && p0 - 1 < S) ? targets[base + (p0 - 1) * F_DIM] : -1;
        #pragma unroll
        for (int i = 0; i < 4; ++i) {
            int p = p0 + i;
            int l = (p < S) ? targets[base + p * F_DIM] : 0;
            labB[i] = (l != 0);
            skA[i]  = (p >= 1 && p < S && l != prev) ? 1.0f : 0.0f;
            prev = l;
        }
    }
    __syncwarp();

    // ---- init at t=0 ----
    float ae0 = 0.f, ae1 = 0.f, ae2 = 0.f, ae3 = 0.f;
    float ao0 = 0.f, ao1 = 0.f, ao2 = 0.f, ao3 = 0.f;
    if (lane == 0) {
        float4 q = Pw[0];
        ae0 = q.z;
        ao0 = labB[0] ? q.y : q.x;
    }
    int   R    = 0;
    float scIn = 0.0f;
    float aoIn;   // neighbor's ao3, carried across steps

#define NORM()                                                                  \
    {                                                                           \
        float mv = fmaxf(fmaxf(fmaxf(ae0, ao0), fmaxf(ae1, ao1)),               \
                         fmaxf(fmaxf(ae2, ao2), fmaxf(ae3, ao3)));              \
        int C = (mv > 0.0f)                                                     \
              ? (R + (int)((__float_as_uint(mv) >> 23) & 255u) - 127)           \
              : CDEAD;                                                          \
        _Pragma("unroll")                                                       \
        for (int o = 1; o < 32; o <<= 1) {                                      \
            int cu = __shfl_up_sync(0xffffffffu, C, o);                         \
            if (lane >= o) C = max(C, cu - DRIFT_T * o);                        \
        }                                                                       \
        int Rn = C;                                                             \
        int Rp = __shfl_up_sync(0xffffffffu, Rn, 1);                            \
        if (lane == 0) Rp = Rn - 200;                                           \
        int d = Rp - Rn;                                                        \
        scIn = (d < -127) ? 0.0f : pow2i(min(d, 127));                          \
        int sh = R - Rn;                                                        \
        int sa = max(-127, min(127, sh));                                       \
        int sb = max(-127, min(127, sh - sa));                                  \
        float fa = pow2i(sa), fb = pow2i(sb);                                   \
        float ff = fa; /* apply in two exact steps */                           \
        ae0 = (ae0*ff)*fb; ae1 = (ae1*ff)*fb; ae2 = (ae2*ff)*fb; ae3 = (ae3*ff)*fb; \
        ao0 = (ao0*ff)*fb; ao1 = (ao1*ff)*fb; ao2 = (ao2*ff)*fb; ao3 = (ao3*ff)*fb; \
        R = Rn;                                                                 \
        aoIn = __shfl_up_sync(0xffffffffu, ao3, 1);                             \
        if (lane == 0) aoIn = 0.0f;                                             \
    }

    // One step. Pair 3 computed FIRST; its shfl issued immediately, consumed
    // only next iteration. aoIn/t1 feed pair 0 of THIS iteration.
#define STEP(tt)                                                                \
    {                                                                           \
        float4 p4 = Pw[tt];                                                     \
        float q0 = p4.x, q1 = p4.y, pb = p4.z;                                  \
        float t1 = aoIn * scIn;                                                 \
        float pl3 = labB[3] ? q1 : q0;                                          \
        float nae3 = (ae3 + ao2) * pb;                                          \
        float nao3 = __fmaf_rn(skA[3], ao2, ao3 + ae3) * pl3;                   \
        float aoN = __shfl_up_sync(0xffffffffu, nao3, 1);                       \
        float pl0 = labB[0] ? q1 : q0;                                          \
        float pl1 = labB[1] ? q1 : q0;                                          \
        float pl2 = labB[2] ? q1 : q0;                                          \
        float nae0 = (ae0 + t1)  * pb;                                          \
        float nao0 = __fmaf_rn(skA[0], t1,  ao0 + ae0) * pl0;                   \
        float nae1 = (ae1 + ao0) * pb;                                          \
        float nao1 = __fmaf_rn(skA[1], ao0, ao1 + ae1) * pl1;                   \
        float nae2 = (ae2 + ao1) * pb;                                          \
        float nao2 = __fmaf_rn(skA[2], ao1, ao2 + ae2) * pl2;                   \
        ae0 = nae0; ae1 = nae1; ae2 = nae2; ae3 = nae3;                         \
        ao0 = nao0; ao1 = nao1; ao2 = nao2; ao3 = nao3;                         \
        aoIn = (lane == 0) ? 0.0f : aoN;                                        \
    }

    NORM();   // sets scIn and aoIn for the first window

    const int Tin = input_lengths[b];
    int t = 1;
    while (t + 8 <= Tin) {
        #pragma unroll
        for (int j = 0; j < 8; ++j) STEP(t + j);
        t += 8;
        NORM();
    }
    for (; t < Tin; ++t) STEP(t);

    // ---- spill finals; lane 0 finalizes this task ----
    AeF[w][p0 + 0] = ae0; AeF[w][p0 + 1] = ae1; AeF[w][p0 + 2] = ae2; AeF[w][p0 + 3] = ae3;
    AoF[w][p0 + 0] = ao0; AoF[w][p0 + 1] = ao1; AoF[w][p0 + 2] = ao2; AoF[w][p0 + 3] = ao3;
    RF[w][lane] = R;
    __syncwarp();

    if (lane == 0 && live) {
        int   Lt = target_lengths[b];
        float v1 = AeF[w][Lt];     int r1 = RF[w][Lt >> 2];
        float v2 = AoF[w][Lt - 1]; int r2 = RF[w][(Lt - 1) >> 2];
        int   Rm = max(r1, r2);
        float w1 = (r1 - Rm < -127) ? 0.0f : pow2i(r1 - Rm);
        float w2 = (r2 - Rm < -127) ? 0.0f : pow2i(r2 - Rm);
        float v  = v1 * w1 + v2 * w2;
        float ll2  = lg2f(v) + (float)Rm;
        float loss = -ll2 * LN2;
        if (!(loss <= 0.5e30f)) loss = 0.0f;   // zero_infinity (also nan/inf)
        g_partials[task] = loss / (float)Lt;
    }
    __syncthreads();

    // ---- fused deterministic reduction (last CTA) ----
    bool isLast = false;
    if (tid == 0) {
        __threadfence();
        int old = atomicAdd(&g_count, 1);
        isLast = (old == (int)gridDim.x - 1);
    }
    if (tid < 32) {
        int last = __shfl_sync(0xffffffffu, isLast ? 1 : 0, 0);
        if (last) {
            float sv = 0.0f;
            for (int j = lane; j < nTasks; j += 32) sv += g_partials[j];
            #pragma unroll
            for (int o = 16; o; o >>= 1) sv += __shfl_down_sync(0xffffffffu, sv, o);
            if (lane == 0) {
                out[0] = sv / (float)nTasks;
                g_count = 0;               // reset for next graph replay
            }
        }
    }
#undef STEP
#undef NORM
}

extern "C" void kernel_launch(void* const* d_in, const int* in_sizes, int n_in,
                              void* d_out, int out_size)
{
    const float* logits  = (const float*)d_in[0];
    const float* blankl  = (const float*)d_in[1];
    const int*   targets = (const int*)d_in[2];
    const int*   in_len  = (const int*)d_in[3];
    const int*   tg_len  = (const int*)d_in[4];

    const int B = in_sizes[3];
    const int T = in_sizes[0] / (B * F_DIM);
    const int S = in_sizes[2] / (B * F_DIM);
    const int nTasks = B * F_DIM;
    const int nblk   = (nTasks + 3) / 4;

    sctc_warp_kernel<<<nblk, 128>>>(logits, blankl, targets, in_len, tg_len,
                                    (float*)d_out, B, T, S, nTasks);
}

// round 9
// speedup vs baseline: 2.0746x; 1.0601x over previous
#include <cuda_runtime.h>
#include <cuda_bf16.h>

#define F_DIM   35
#define T_PAD   512
#define LOG2E   1.4426950408889634f
#define LN2     0.6931471805599453f
#define CDEAD   (-(1 << 28))
#define DRIFT_T 48

__device__ float g_partials[1024];
__device__ int   g_count = 0;

__device__ __forceinline__ float ex2f(float x) {
    float r; asm("ex2.approx.ftz.f32 %0, %1;" : "=f"(r) : "f"(x)); return r;
}
__device__ __forceinline__ float lg2f(float x) {
    float r; asm("lg2.approx.ftz.f32 %0, %1;" : "=f"(r) : "f"(x)); return r;
}
__device__ __forceinline__ float pow2i(int e) {   // 2^e, e in [-127,128]
    return __uint_as_float((unsigned)(127 + e) << 23);
}

// One WARP per (b,f) task; thread owns 4 state-pairs. Linear-domain CTC with
// per-thread power-of-2 refs, re-smoothed every 8 frames by a FRESH-VALUE
// in-warp scan (R7 semantics — proven correct). Scheduling: the window's 8
// prob float4s are preloaded into registers BEFORE the scan (LDS drains under
// the serial shfl chain); STEP is phase-batched; the cross-lane shfl result is
// carried raw and selected late, one full step downstream of its producer.
__global__ __launch_bounds__(128, 1) void sctc_warp_kernel(
    const float* __restrict__ logits,        // (B,T,F)
    const float* __restrict__ blank_logit,   // (1,)
    const int*   __restrict__ targets,       // (B,S,F)
    const int*   __restrict__ input_lengths, // (B,)
    const int*   __restrict__ target_lengths,// (B,)
    float* __restrict__ out,
    int B, int T, int S, int nTasks)
{
    __shared__ float4 P4[4][T_PAD];    // per-warp {q0, q1, pb, pad}
    __shared__ float  AeF[4][128];
    __shared__ float  AoF[4][128];
    __shared__ int    RF[4][32];

    const int tid  = threadIdx.x;
    const int lane = tid & 31;
    const int w    = tid >> 5;
    int  task = blockIdx.x * 4 + w;
    bool live = (task < nTasks);
    if (!live) task = 0;
    const int b = task / F_DIM;
    const int f = task - b * F_DIM;

    const float ub = blank_logit[0] * LOG2E;
    float4* Pw = P4[w];

    // ---- linear 3-class softmax, packed ----
    for (int t = lane; t < T; t += 32) {
        float u  = logits[(b * T + t) * F_DIM + f] * LOG2E;
        float m  = fmaxf(fabsf(u), ub);
        float s0 = ex2f(-u - m);
        float s1 = ex2f( u - m);
        float s2 = ex2f(ub - m);
        float iv = 1.0f / (s0 + s1 + s2);
        Pw[t] = make_float4(s0 * iv, s1 * iv, s2 * iv, 0.0f);
    }

    // ---- per-pair structure ----
    const int p0 = lane * 4;
    bool  labB[4];
    float skA[4];
    {
        const int base = b * S * F_DIM + f;
        int prev = (p0 >= 1 && p0 - 1 < S) ? targets[base + (p0 - 1) * F_DIM] : -1;
        #pragma unroll
        for (int i = 0; i < 4; ++i) {
            int p = p0 + i;
            int l = (p < S) ? targets[base + p * F_DIM] : 0;
            labB[i] = (l != 0);
            skA[i]  = (p >= 1 && p < S && l != prev) ? 1.0f : 0.0f;
            prev = l;
        }
    }
    __syncwarp();

    // ---- init at t=0 ----
    float ae0 = 0.f, ae1 = 0.f, ae2 = 0.f, ae3 = 0.f;
    float ao0 = 0.f, ao1 = 0.f, ao2 = 0.f, ao3 = 0.f;
    if (lane == 0) {
        float4 q = Pw[0];
        ae0 = q.z;
        ao0 = labB[0] ? q.y : q.x;
    }
    int   R     = 0;
    float scIn  = 0.0f;
    float aoRaw = 0.0f;   // raw shfl of neighbor's ao3 (lane0 content unused)
    const bool lz = (lane == 0);

    // One step, phase-batched. aoRaw/scIn feed pair 0 of THIS step (lane-0
    // zeroing folded into t1); the shfl of nao3 is issued mid-step and its
    // result consumed only next step.
#define STEP(q4)                                                                \
    {                                                                           \
        float q0 = (q4).x, q1 = (q4).y, pb = (q4).z;                            \
        float t1 = lz ? 0.0f : aoRaw * scIn;                                    \
        float se0 = ae0 + t1;                                                   \
        float se1 = ae1 + ao0;                                                  \
        float se2 = ae2 + ao1;                                                  \
        float se3 = ae3 + ao2;                                                  \
        float so0 = ao0 + ae0;                                                  \
        float so1 = ao1 + ae1;                                                  \
        float so2 = ao2 + ae2;                                                  \
        float so3 = ao3 + ae3;                                                  \
        so3 = __fmaf_rn(skA[3], ao2, so3);                                      \
        float pl3 = labB[3] ? q1 : q0;                                          \
        float nao3 = so3 * pl3;                                                 \
        float aoN = __shfl_up_sync(0xffffffffu, nao3, 1);                       \
        so0 = __fmaf_rn(skA[0], t1,  so0);                                      \
        so1 = __fmaf_rn(skA[1], ao0, so1);                                      \
        so2 = __fmaf_rn(skA[2], ao1, so2);                                      \
        float pl0 = labB[0] ? q1 : q0;                                          \
        float pl1 = labB[1] ? q1 : q0;                                          \
        float pl2 = labB[2] ? q1 : q0;                                          \
        ae0 = se0 * pb; ae1 = se1 * pb; ae2 = se2 * pb; ae3 = se3 * pb;         \
        ao0 = so0 * pl0; ao1 = so1 * pl1; ao2 = so2 * pl2; ao3 = nao3;          \
        aoRaw = aoN;                                                            \
    }

    // Fresh-value normalize (R7 semantics): scan current exponents, rescale
    // immediately, refresh scIn and aoRaw in the new scale.
#define NORM()                                                                  \
    {                                                                           \
        float mv = fmaxf(fmaxf(fmaxf(ae0, ao0), fmaxf(ae1, ao1)),               \
                         fmaxf(fmaxf(ae2, ao2), fmaxf(ae3, ao3)));              \
        int C = (mv > 0.0f)                                                     \
              ? (R + (int)((__float_as_uint(mv) >> 23) & 255u) - 127)           \
              : CDEAD;                                                          \
        _Pragma("unroll")                                                       \
        for (int o = 1; o < 32; o <<= 1) {                                      \
            int cu = __shfl_up_sync(0xffffffffu, C, o);                         \
            if (lane >= o) C = max(C, cu - DRIFT_T * (o));                      \
        }                                                                       \
        int Rn = C;                                                             \
        int Rp = __shfl_up_sync(0xffffffffu, Rn, 1);                            \
        if (lz) Rp = Rn - 200;                                                  \
        int d = Rp - Rn;                                                        \
        scIn = (d < -127) ? 0.0f : pow2i(min(d, 127));                          \
        int sh = R - Rn;                                                        \
        int sa = max(-127, min(127, sh));                                       \
        int sb = max(-127, min(127, sh - sa));                                  \
        float fa = pow2i(sa), fb = pow2i(sb);                                   \
        ae0 = (ae0*fa)*fb; ae1 = (ae1*fa)*fb; ae2 = (ae2*fa)*fb; ae3 = (ae3*fa)*fb; \
        ao0 = (ao0*fa)*fb; ao1 = (ao1*fa)*fb; ao2 = (ao2*fa)*fb; ao3 = (ao3*fa)*fb; \
        R = Rn;                                                                 \
        aoRaw = __shfl_up_sync(0xffffffffu, ao3, 1);                            \
    }

    NORM();   // establishes scIn / aoRaw for the first window

    const int Tin = input_lengths[b];
    int t = 1;
    while (t + 8 <= Tin) {
        // Preload the window's probs FIRST: the 8 independent LDS.128s drain
        // underneath the following steps' FP work and the next NORM's scan.
        float4 q[8];
        #pragma unroll
        for (int j = 0; j < 8; ++j) q[j] = Pw[t + j];

        #pragma unroll
        for (int j = 0; j < 8; ++j) STEP(q[j]);
        t += 8;
        NORM();
    }
    for (; t < Tin; ++t) { float4 q4 = Pw[t]; STEP(q4); }

    // ---- spill finals; lane 0 finalizes this task ----
    AeF[w][p0 + 0] = ae0; AeF[w][p0 + 1] = ae1; AeF[w][p0 + 2] = ae2; AeF[w][p0 + 3] = ae3;
    AoF[w][p0 + 0] = ao0; AoF[w][p0 + 1] = ao1; AoF[w][p0 + 2] = ao2; AoF[w][p0 + 3] = ao3;
    RF[w][lane] = R;
    __syncwarp();

    if (lane == 0 && live) {
        int   Lt = target_lengths[b];
        float v1 = AeF[w][Lt];     int r1 = RF[w][Lt >> 2];
        float v2 = AoF[w][Lt - 1]; int r2 = RF[w][(Lt - 1) >> 2];
        int   Rm = max(r1, r2);
        float w1 = (r1 - Rm < -127) ? 0.0f : pow2i(r1 - Rm);
        float w2 = (r2 - Rm < -127) ? 0.0f : pow2i(r2 - Rm);
        float v  = v1 * w1 + v2 * w2;
        float ll2  = lg2f(v) + (float)Rm;
        float loss = -ll2 * LN2;
        if (!(loss <= 0.5e30f)) loss = 0.0f;   // zero_infinity (also nan/inf)
        g_partials[task] = loss / (float)Lt;
    }
    __syncthreads();

    // ---- fused deterministic reduction (last CTA) ----
    bool isLast = false;
    if (tid == 0) {
        __threadfence();
        int old = atomicAdd(&g_count, 1);
        isLast = (old == (int)gridDim.x - 1);
    }
    if (tid < 32) {
        int last = __shfl_sync(0xffffffffu, isLast ? 1 : 0, 0);
        if (last) {
            float sv = 0.0f;
            for (int j = lane; j < nTasks; j += 32) sv += g_partials[j];
            #pragma unroll
            for (int o = 16; o; o >>= 1) sv += __shfl_down_sync(0xffffffffu, sv, o);
            if (lane == 0) {
                out[0] = sv / (float)nTasks;
                g_count = 0;               // reset for next graph replay
            }
        }
    }
#undef STEP
#undef NORM
}

extern "C" void kernel_launch(void* const* d_in, const int* in_sizes, int n_in,
                              void* d_out, int out_size)
{
    const float* logits  = (const float*)d_in[0];
    const float* blankl  = (const float*)d_in[1];
    const int*   targets = (const int*)d_in[2];
    const int*   in_len  = (const int*)d_in[3];
    const int*   tg_len  = (const int*)d_in[4];

    const int B = in_sizes[3];
    const int T = in_sizes[0] / (B * F_DIM);
    const int S = in_sizes[2] / (B * F_DIM);
    const int nTasks = B * F_DIM;
    const int nblk   = (nTasks + 3) / 4;

    sctc_warp_kernel<<<nblk, 128>>>(logits, blankl, targets, in_len, tg_len,
                                    (float*)d_out, B, T, S, nTasks);
}